// round 17
// baseline (speedup 1.0000x reference)
#include <cuda_runtime.h>
#include <cuda_fp16.h>

#define NN 50000
#define EMB 35
#define DEG 32
#define HPAD 64      // fp16 row pad: 64 halves = 128 B
#define APAD 36      // fp32 padded row: 36 floats

typedef unsigned long long ull;

// ---- prep buffer layout (floats) ----
#define WCSZ  (36*72)
#define VOFF  (4*WCSZ)
#define COFF  (VOFF + 4*EMB)
#define BOFF  (COFF + 4)
#define PREPN (BOFF + 144)

__device__ float  g_prep[PREPN];
__device__ __half g_h16[2*NN*HPAD];
__device__ float  g_f36[2*NN*APAD];
__device__ float  g_sc[8*NN];
__device__ float  g_agg0[NN*APAD];
__device__ float  g_agg1[NN*APAD];

__device__ __forceinline__ ull pk(float lo, float hi) {
    ull r; asm("mov.b64 %0,{%1,%2};" : "=l"(r) : "f"(lo), "f"(hi)); return r;
}
__device__ __forceinline__ void upk(ull v, float& lo, float& hi) {
    asm("mov.b64 {%0,%1},%2;" : "=f"(lo), "=f"(hi) : "l"(v));
}
__device__ __forceinline__ void ffma2(ull& d, ull a, ull b) {
    asm("fma.rn.f32x2 %0,%1,%2,%0;" : "+l"(d) : "l"(a), "l"(b));
}

// ============ prep (unchanged) ============
__global__ void prep_kernel(const float* __restrict__ W0, const float* __restrict__ A0, const float* __restrict__ B0,
                            const float* __restrict__ Wt1, const float* __restrict__ A1, const float* __restrict__ B1,
                            const float* __restrict__ Wt2, const float* __restrict__ A2, const float* __restrict__ B2,
                            const float* __restrict__ Wt3, const float* __restrict__ A3, const float* __restrict__ B3,
                            const float* __restrict__ W1, const float* __restrict__ b1) {
    const float* Wt[4] = {W0, Wt1, Wt2, Wt3};
    const float* At[4] = {A0, A1, A2, A3};
    const float* Bt[4] = {B0, B1, B2, B3};
    for (int idx = blockIdx.x * blockDim.x + threadIdx.x; idx < PREPN; idx += gridDim.x * blockDim.x) {
        float val = 0.f;
        if (idx < VOFF) {
            int t = idx / WCSZ, r = idx % WCSZ, k = r / 72, o = r % 72;
            if (k < 35 && o < 70) {
                int mid = (t & 1) ? 70 : 35;
                const float* w = Wt[t] + k * EMB;
                for (int e = 0; e < EMB; e++) val += w[e] * W1[(mid + e) * 70 + o];
            }
        } else if (idx < COFF) {
            int j = idx - VOFF; int t = j / EMB, k = j % EMB;
            const float* w = Wt[t] + k * EMB; const float* a = At[t] + EMB;
            for (int e = 0; e < EMB; e++) val += w[e] * a[e];
        } else if (idx < BOFF) {
            int t = idx - COFF;
            const float* a = At[t] + EMB; const float* bb = Bt[t];
            for (int e = 0; e < EMB; e++) val += bb[e] * a[e];
        } else {
            int j = idx - BOFF; int s = j / 72, o = j % 72;
            if (o < 70) {
                val = b1[o];
                const float* bp = Bt[s * 2]; const float* bn = Bt[s * 2 + 1];
                for (int e = 0; e < EMB; e++)
                    val += bp[e] * W1[(35 + e) * 70 + o] + bn[e] * W1[(70 + e) * 70 + o];
            }
        }
        g_prep[idx] = val;
    }
}

// ============ encode (unchanged) ============
__global__ void encode_kernel(const float* __restrict__ fa, const float* __restrict__ fb,
                              const float* __restrict__ att0, const float* __restrict__ att1,
                              const float* __restrict__ att2, const float* __restrict__ att3) {
    int i = blockIdx.x * blockDim.x + threadIdx.x;
    if (i >= 2 * NN) return;
    int side = (i >= NN) ? 1 : 0;
    int node = side ? i - NN : i;
    const float* src = (side ? fb : fa) + (size_t)node * EMB;

    float x[EMB];
#pragma unroll
    for (int k = 0; k < EMB; k++) x[k] = src[k];

    unsigned u[32];
#pragma unroll
    for (int p = 0; p < 32; p++) {
        float lo = (2 * p     < EMB) ? x[2 * p]     : 0.f;
        float hi = (2 * p + 1 < EMB) ? x[2 * p + 1] : 0.f;
        __half2 hh = __floats2half2_rn(lo, hi);
        u[p] = *reinterpret_cast<unsigned*>(&hh);
    }
    uint4* orow = reinterpret_cast<uint4*>(g_h16 + (size_t)i * HPAD);
#pragma unroll
    for (int q = 0; q < 8; q++) orow[q] = make_uint4(u[4 * q], u[4 * q + 1], u[4 * q + 2], u[4 * q + 3]);

    float* frow = g_f36 + (size_t)i * APAD;
#pragma unroll
    for (int k = 0; k < EMB; k++) frow[k] = x[k];
    frow[35] = 0.f;

    const float* v0 = g_prep + VOFF;
    const float* v1 = g_prep + VOFF + EMB;
    const float* v2 = g_prep + VOFF + 2 * EMB;
    const float* v3 = g_prep + VOFF + 3 * EMB;
    float s0 = 0.f, s1 = 0.f, s2, s3;
    if (!side) {
        s2 = g_prep[COFF + 2]; s3 = g_prep[COFF + 3];
#pragma unroll
        for (int k = 0; k < EMB; k++) {
            s0 += x[k] * att0[k]; s1 += x[k] * att1[k];
            s2 += x[k] * v2[k];   s3 += x[k] * v3[k];
        }
        g_sc[0 * NN + node] = s0;
        g_sc[1 * NN + node] = s1;
        g_sc[6 * NN + node] = s2;
        g_sc[7 * NN + node] = s3;
    } else {
        s2 = g_prep[COFF + 0]; s3 = g_prep[COFF + 1];
#pragma unroll
        for (int k = 0; k < EMB; k++) {
            s0 += x[k] * att2[k]; s1 += x[k] * att3[k];
            s2 += x[k] * v0[k];   s3 += x[k] * v1[k];
        }
        g_sc[2 * NN + node] = s0;
        g_sc[3 * NN + node] = s1;
        g_sc[4 * NN + node] = s2;
        g_sc[5 * NN + node] = s3;
    }
}

// ============ aggregate2 v2: half2-lane layout, lane<18 owns dims (2l,2l+1) ============
__global__ void aggregate2_kernel(const float* __restrict__ sa0, const float* __restrict__ sa1,
                                  const float* __restrict__ sb0, const float* __restrict__ sb1,
                                  const int* __restrict__ dst0, const int* __restrict__ dst1,
                                  const __half* __restrict__ src,
                                  float* __restrict__ out0, float* __restrict__ out1) {
    int warp = (blockIdx.x * blockDim.x + threadIdx.x) >> 5;
    int lane = threadIdx.x & 31;
    if (warp >= NN) return;

    float a0s = sa0[warp], a1s = sa1[warp];
    int d0 = dst0[warp * DEG + lane];
    int d1 = dst1[warp * DEG + lane];
    float s0 = a0s + sb0[d0], s1 = a1s + sb1[d1];
    float e0 = s0 > 0.f ? s0 : 0.1f * expm1f(s0);
    float e1 = s1 > 0.f ? s1 : 0.1f * expm1f(s1);
    float w0 = __expf(e0), w1 = __expf(e1);

    float den0 = w0, den1 = w1;
#pragma unroll
    for (int o = 16; o; o >>= 1) {
        den0 += __shfl_xor_sync(0xffffffffu, den0, o);
        den1 += __shfl_xor_sync(0xffffffffu, den1, o);
    }

    float2 A0 = {0.f, 0.f}, A1 = {0.f, 0.f};
    const unsigned* b32 = reinterpret_cast<const unsigned*>(src);   // 32 half2 per row
#pragma unroll
    for (int j = 0; j < DEG; j++) {
        float wj0 = __shfl_sync(0xffffffffu, w0, j);
        int   dj0 = __shfl_sync(0xffffffffu, d0, j);
        float wj1 = __shfl_sync(0xffffffffu, w1, j);
        int   dj1 = __shfl_sync(0xffffffffu, d1, j);
        if (lane < 18) {
            unsigned u0 = b32[(size_t)dj0 * 32 + lane];
            unsigned u1 = b32[(size_t)dj1 * 32 + lane];
            float2 f0 = __half22float2(*reinterpret_cast<__half2*>(&u0));
            float2 f1 = __half22float2(*reinterpret_cast<__half2*>(&u1));
            A0.x = fmaf(wj0, f0.x, A0.x); A0.y = fmaf(wj0, f0.y, A0.y);
            A1.x = fmaf(wj1, f1.x, A1.x); A1.y = fmaf(wj1, f1.y, A1.y);
        }
    }
    if (lane < 18) {   // covers dims 0..35 (dim 35 is zero-pad, rows zero there)
        float i0 = 1.f / den0, i1 = 1.f / den1;
        reinterpret_cast<float2*>(out0 + (size_t)warp * APAD)[lane] = make_float2(A0.x * i0, A0.y * i0);
        reinterpret_cast<float2*>(out1 + (size_t)warp * APAD)[lane] = make_float2(A1.x * i1, A1.y * i1);
    }
}

// ============ update v2: smem-tiled GEMM (64 rows/block, 144 thr, 8x4 / 8x2 tiles) ============
#define UBR 64
#define UT  144

__global__ void __launch_bounds__(UT) update_kernel(
        const float* __restrict__ fsrc,
        const float* __restrict__ aggp, const float* __restrict__ aggn,
        const float* __restrict__ W1,
        const float* __restrict__ Wcp, const float* __restrict__ Wcn,
        const float* __restrict__ bfold,
        const float* __restrict__ alpha,
        const float* __restrict__ W2, const float* __restrict__ b2,
        float* __restrict__ out) {
    // Region A: phase1 = W1comp [105][72] f32 (30240 B); phase2 = h [70][64] f16 (8960) + W2 [70][36] f32 (10080 @ +8960)
    __shared__ __align__(16) char sRA[30240];
    // Region B: X [105][72] f16 (15120 B)
    __shared__ __align__(16) char sRB[15120];
    __shared__ float sbf[72];
    __shared__ float sb2s[36];
    __shared__ float salpha;

    float*  sW1 = reinterpret_cast<float*>(sRA);
    __half* sX  = reinterpret_cast<__half*>(sRB);
    __half* sh  = reinterpret_cast<__half*>(sRA);
    float*  sW2 = reinterpret_cast<float*>(sRA + 8960);

    int tid = threadIdx.x;
    size_t row0 = (size_t)blockIdx.x * UBR;

    // ---- stage composite W1 [105][72] ----
    for (int i = tid; i < 105 * 72; i += UT) {
        int k = i / 72, o = i % 72;
        float v;
        if (k < 35)      v = (o < 70) ? W1[k * 70 + o] : 0.f;
        else if (k < 70) v = Wcp[(k - 35) * 72 + o];
        else             v = Wcn[(k - 70) * 72 + o];
        sW1[i] = v;
    }
    if (tid < 72) sbf[tid] = bfold[tid];
    if (tid < 36) sb2s[tid] = (tid < 35) ? b2[tid] : 0.f;
    if (tid == 0) salpha = alpha[0];

    // ---- stage X^T [105][72] fp16 (only cols 0..63 used) ----
    for (int e = tid; e < UBR * 105; e += UT) {
        int r = e / 105, k = e % 105;
        size_t row = row0 + r;
        float v = 0.f;
        if (row < NN) {
            if (k < 35)      v = fsrc[row * APAD + k];
            else if (k < 70) v = aggp[row * APAD + (k - 35)];
            else             v = aggn[row * APAD + (k - 70)];
        }
        sX[k * 72 + r] = __float2half(v);
    }
    __syncthreads();

    // ---- phase 1: h = X @ W1comp + bfold ; thread tile 8 rows x 4 cols ----
    int rg = tid & 7, cg = tid >> 3;       // rg 0..7, cg 0..17
    int r0 = rg * 8, c0 = cg * 4;

    ull acc[4][4];
#pragma unroll
    for (int c = 0; c < 4; c++) {
        float b = sbf[c0 + c];
        ull bb = pk(b, b);
#pragma unroll
        for (int p = 0; p < 4; p++) acc[c][p] = bb;
    }
    for (int k = 0; k < 105; k++) {
        uint4  xu = *reinterpret_cast<const uint4*>(sX + k * 72 + r0);     // 8 halves (rows r0..r0+7)
        float4 wv = *reinterpret_cast<const float4*>(sW1 + k * 72 + c0);   // 4 cols
        float2 f0 = __half22float2(*reinterpret_cast<__half2*>(&xu.x));
        float2 f1 = __half22float2(*reinterpret_cast<__half2*>(&xu.y));
        float2 f2 = __half22float2(*reinterpret_cast<__half2*>(&xu.z));
        float2 f3 = __half22float2(*reinterpret_cast<__half2*>(&xu.w));
        ull x2[4] = { pk(f0.x, f0.y), pk(f1.x, f1.y), pk(f2.x, f2.y), pk(f3.x, f3.y) };
        ull w2[4] = { pk(wv.x, wv.x), pk(wv.y, wv.y), pk(wv.z, wv.z), pk(wv.w, wv.w) };
#pragma unroll
        for (int c = 0; c < 4; c++)
#pragma unroll
            for (int p = 0; p < 4; p++)
                ffma2(acc[c][p], x2[p], w2[c]);
    }
    float al = salpha;
    __syncthreads();   // all reads of sW1/sX done before overlay

    // ---- PReLU, stage h [70][64] fp16; cooperative load W2 ----
#pragma unroll
    for (int c = 0; c < 4; c++) {
        int col = c0 + c;
        if (col < 70) {
#pragma unroll
            for (int p = 0; p < 4; p++) {
                float lo, hi; upk(acc[c][p], lo, hi);
                lo = lo > 0.f ? lo : al * lo;
                hi = hi > 0.f ? hi : al * hi;
                *reinterpret_cast<__half2*>(sh + col * 64 + r0 + 2 * p) = __floats2half2_rn(lo, hi);
            }
        }
    }
    for (int i = tid; i < 70 * 36; i += UT) {
        int k = i / 36, o = i % 36;
        sW2[i] = (o < 35) ? W2[k * 35 + o] : 0.f;
    }
    __syncthreads();

    // ---- phase 2: out = prelu_h @ W2 + b2 ; thread tile 8 rows x 2 cols ----
    int c02 = cg * 2;
    ull acc2[2][4];
#pragma unroll
    for (int c = 0; c < 2; c++) {
        float b = sb2s[c02 + c];
        ull bb = pk(b, b);
#pragma unroll
        for (int p = 0; p < 4; p++) acc2[c][p] = bb;
    }
    for (int k = 0; k < 70; k++) {
        uint4  xu = *reinterpret_cast<const uint4*>(sh + k * 64 + r0);
        float2 wv = *reinterpret_cast<const float2*>(sW2 + k * 36 + c02);
        float2 f0 = __half22float2(*reinterpret_cast<__half2*>(&xu.x));
        float2 f1 = __half22float2(*reinterpret_cast<__half2*>(&xu.y));
        float2 f2 = __half22float2(*reinterpret_cast<__half2*>(&xu.z));
        float2 f3 = __half22float2(*reinterpret_cast<__half2*>(&xu.w));
        ull x2[4] = { pk(f0.x, f0.y), pk(f1.x, f1.y), pk(f2.x, f2.y), pk(f3.x, f3.y) };
        ull w0 = pk(wv.x, wv.x), w1 = pk(wv.y, wv.y);
#pragma unroll
        for (int p = 0; p < 4; p++) {
            ffma2(acc2[0][p], x2[p], w0);
            ffma2(acc2[1][p], x2[p], w1);
        }
    }
#pragma unroll
    for (int c = 0; c < 2; c++) {
        int col = c02 + c;
        if (col < 35) {
#pragma unroll
            for (int p = 0; p < 4; p++) {
                float lo, hi; upk(acc2[c][p], lo, hi);
                size_t ra = row0 + r0 + 2 * p;
                if (ra < NN)     out[ra * EMB + col] = lo;
                if (ra + 1 < NN) out[(ra + 1) * EMB + col] = hi;
            }
        }
    }
}

// ============ launch ============
extern "C" void kernel_launch(void* const* d_in, const int* in_sizes, int n_in,
                              void* d_out, int out_size) {
    const float* fa    = (const float*)d_in[0];
    const float* fb    = (const float*)d_in[1];
    const int*   dab_p = (const int*)  d_in[2];
    const int*   dab_n = (const int*)  d_in[3];
    const int*   dba_p = (const int*)  d_in[4];
    const int*   dba_n = (const int*)  d_in[5];
    const float* W_abp = (const float*)d_in[6];
    const float* b_abp = (const float*)d_in[7];
    const float* a_abp = (const float*)d_in[8];
    const float* W_abn = (const float*)d_in[9];
    const float* b_abn = (const float*)d_in[10];
    const float* a_abn = (const float*)d_in[11];
    const float* W_bap = (const float*)d_in[12];
    const float* b_bap = (const float*)d_in[13];
    const float* a_bap = (const float*)d_in[14];
    const float* W_ban = (const float*)d_in[15];
    const float* b_ban = (const float*)d_in[16];
    const float* a_ban = (const float*)d_in[17];
    const float* W1    = (const float*)d_in[18];
    const float* b1    = (const float*)d_in[19];
    const float* alpha = (const float*)d_in[20];
    const float* W2    = (const float*)d_in[21];
    const float* b2    = (const float*)d_in[22];
    float* out = (float*)d_out;

    float *prep, *f36, *sc, *agg0, *agg1;
    __half* h16;
    cudaGetSymbolAddress((void**)&prep, g_prep);
    cudaGetSymbolAddress((void**)&h16,  g_h16);
    cudaGetSymbolAddress((void**)&f36,  g_f36);
    cudaGetSymbolAddress((void**)&sc,   g_sc);
    cudaGetSymbolAddress((void**)&agg0, g_agg0);
    cudaGetSymbolAddress((void**)&agg1, g_agg1);

    prep_kernel<<<48, 256>>>(W_abp, a_abp, b_abp, W_abn, a_abn, b_abn,
                             W_bap, a_bap, b_bap, W_ban, a_ban, b_ban, W1, b1);
    encode_kernel<<<(2 * NN + 255) / 256, 256>>>(fa, fb, a_abp, a_abn, a_bap, a_ban);

    int ugrid = (NN + UBR - 1) / UBR;

    // side A: dest=A, source=B rows
    aggregate2_kernel<<<(NN * 32 + 255) / 256, 256>>>(
        sc + 0 * NN, sc + 1 * NN, sc + 4 * NN, sc + 5 * NN,
        dab_p, dab_n, h16 + (size_t)NN * HPAD, agg0, agg1);
    update_kernel<<<ugrid, UT>>>(
        f36, agg0, agg1, W1,
        prep + 0 * WCSZ, prep + 1 * WCSZ, prep + BOFF,
        alpha, W2, b2, out);

    // side B: dest=B, source=A rows
    aggregate2_kernel<<<(NN * 32 + 255) / 256, 256>>>(
        sc + 2 * NN, sc + 3 * NN, sc + 6 * NN, sc + 7 * NN,
        dba_p, dba_n, h16, agg0, agg1);
    update_kernel<<<ugrid, UT>>>(
        f36 + (size_t)NN * APAD, agg0, agg1, W1,
        prep + 2 * WCSZ, prep + 3 * WCSZ, prep + BOFF + 72,
        alpha, W2, b2, out + (size_t)NN * EMB);

    (void)in_sizes; (void)n_in; (void)out_size;
}